// round 1
// baseline (speedup 1.0000x reference)
#include <cuda_runtime.h>

// ---------------------------------------------------------------------------
// GIN: 3-layer, N=50000 nodes, E=625000 edges, H=128.
// Restructured:
//   ea_agg-through-encoder: eam[i] = (seg_attr[i] @ edge_W) * inv_deg[i]
//                                    + (deg[i]>0 ? edge_b : 0)
//   per layer: h = (1+eps)*x + agg_x*inv_deg + eam ; x = relu(relu(h@W1+b1)@W2+b2)
// All fp32 this round (establish correctness + rel_err headroom).
// ---------------------------------------------------------------------------

#define NN     50000
#define EE     625000
#define IN_EDGE 64
#define HH     128
#define HH2    256
#define OUTD   112

// scratch (device globals; no allocation allowed)
__device__ float g_x  [NN * HH];
__device__ float g_h1 [NN * HH2];
__device__ float g_agg[NN * HH];
__device__ float g_eam[NN * HH];
__device__ float g_seg[NN * IN_EDGE];
__device__ float g_deg[NN];
__device__ float g_inv[NN];

__device__ __forceinline__ void red_add_v4(float* addr, float4 v) {
    asm volatile("red.global.add.v4.f32 [%0], {%1,%2,%3,%4};"
                 :: "l"(addr), "f"(v.x), "f"(v.y), "f"(v.z), "f"(v.w)
                 : "memory");
}

__global__ void zero_kernel(float* __restrict__ p, int n) {
    int i = blockIdx.x * blockDim.x + threadIdx.x;
    int stride = gridDim.x * blockDim.x;
    for (; i < n; i += stride) p[i] = 0.f;
}

__global__ void deg_kernel(const int* __restrict__ ei, float* __restrict__ deg) {
    int e = blockIdx.x * blockDim.x + threadIdx.x;
    if (e < EE) atomicAdd(&deg[ei[EE + e]], 1.0f);
}

__global__ void inv_kernel(const float* __restrict__ deg, float* __restrict__ inv) {
    int i = blockIdx.x * blockDim.x + threadIdx.x;
    if (i < NN) inv[i] = 1.0f / fmaxf(deg[i], 1.0f);
}

// seg_attr[dst] += edge_attr[e]  (16 threads per edge, float4 each)
__global__ void seg_scatter_kernel(const float* __restrict__ ea,
                                   const int* __restrict__ ei,
                                   float* __restrict__ seg) {
    int gid = blockIdx.x * blockDim.x + threadIdx.x;
    if (gid >= EE * 16) return;
    int e = gid >> 4;
    int g = gid & 15;
    int dst = __ldg(&ei[EE + e]);
    float4 v = __ldg(((const float4*)ea) + (size_t)e * 16 + g);
    red_add_v4(seg + (size_t)dst * IN_EDGE + g * 4, v);
}

// agg[dst] += x[src]  (one warp per edge, float4 per lane). Grid is exact:
// EE*32 threads / 256 = 78125 blocks, so every warp is full.
__global__ void x_scatter_kernel(const int* __restrict__ ei,
                                 const float* __restrict__ x,
                                 float* __restrict__ agg) {
    int gid = blockIdx.x * blockDim.x + threadIdx.x;
    int e = gid >> 5;
    int lane = threadIdx.x & 31;
    int src = 0, dst = 0;
    if (lane == 0) { src = __ldg(&ei[e]); dst = __ldg(&ei[EE + e]); }
    src = __shfl_sync(0xffffffffu, src, 0);
    dst = __shfl_sync(0xffffffffu, dst, 0);
    float4 v = __ldg(((const float4*)x) + (size_t)src * 32 + lane);
    red_add_v4(agg + (size_t)dst * HH + lane * 4, v);
}

// ---------------------------------------------------------------------------
// Register-tiled SGEMM: C = epi(A_eff @ B + bias)
//   BM=BN=64, BK=64, 256 threads, 4x4 micro-tile per thread.
// MODEA: 0 = plain A; 1 = A_eff = (1+eps[l])*x + agg*inv_deg[row] + eam (GIN combine)
// EPI:   0 = +bias; 1 = relu(+bias); 2 = *inv_deg[row] + (deg[row]>0 ? bias : 0)
// K must be a multiple of 64 (64/128/256 here). Row/col guards for M, Nc.
// ---------------------------------------------------------------------------
template <int MODEA, int EPI>
__global__ void __launch_bounds__(256)
gemm_kernel(const float* __restrict__ A, const float* __restrict__ B,
            const float* __restrict__ bias, float* __restrict__ C,
            int M, int K, int Nc,
            const float* __restrict__ agg, const float* __restrict__ eam,
            const float* __restrict__ inv, const float* __restrict__ deg,
            const float* __restrict__ eps_p, int layer) {
    __shared__ float As[64][68];   // transposed: As[k][m]
    __shared__ float Bs[64][68];   // Bs[k][n]

    int tid = threadIdx.x;
    int tx = tid & 15;   // column group (4 cols)
    int ty = tid >> 4;   // row group (4 rows)
    int rowBase = blockIdx.x * 64;
    int colBase = blockIdx.y * 64;

    float acc[4][4] = {};
    float epsv = 0.f;
    if (MODEA == 1) epsv = 1.f + __ldg(&eps_p[layer]);

    for (int kt = 0; kt < K; kt += 64) {
        // ---- load A tile (64 rows x 64 k), store transposed ----
        #pragma unroll
        for (int i = 0; i < 4; i++) {
            int f = tid + i * 256;
            int ar  = f >> 4;     // row within tile
            int ac4 = f & 15;     // k-group of 4
            int gr = rowBase + ar;
            float4 v = make_float4(0.f, 0.f, 0.f, 0.f);
            if (gr < M) {
                size_t off = (size_t)gr * K + kt + ac4 * 4;
                v = __ldg((const float4*)(A + off));
                if (MODEA == 1) {
                    float4 ag = __ldg((const float4*)(agg + off));
                    float4 em = __ldg((const float4*)(eam + off));
                    float iv  = __ldg(&inv[gr]);
                    v.x = epsv * v.x + ag.x * iv + em.x;
                    v.y = epsv * v.y + ag.y * iv + em.y;
                    v.z = epsv * v.z + ag.z * iv + em.z;
                    v.w = epsv * v.w + ag.w * iv + em.w;
                }
            }
            As[ac4 * 4 + 0][ar] = v.x;
            As[ac4 * 4 + 1][ar] = v.y;
            As[ac4 * 4 + 2][ar] = v.z;
            As[ac4 * 4 + 3][ar] = v.w;
        }
        // ---- load B tile (64 k x 64 n) ----
        #pragma unroll
        for (int i = 0; i < 4; i++) {
            int f = tid + i * 256;
            int br  = f >> 4;     // k within tile
            int bc4 = f & 15;     // n-group of 4
            int gk = kt + br;
            int gc = colBase + bc4 * 4;
            float4 v = make_float4(0.f, 0.f, 0.f, 0.f);
            const float* bp = B + (size_t)gk * Nc + gc;
            if (gc + 3 < Nc) {
                v = __ldg((const float4*)bp);
            } else {
                if (gc + 0 < Nc) v.x = __ldg(bp + 0);
                if (gc + 1 < Nc) v.y = __ldg(bp + 1);
                if (gc + 2 < Nc) v.z = __ldg(bp + 2);
                if (gc + 3 < Nc) v.w = __ldg(bp + 3);
            }
            *(float4*)&Bs[br][bc4 * 4] = v;
        }
        __syncthreads();

        #pragma unroll 32
        for (int k = 0; k < 64; k++) {
            float4 a = *(const float4*)&As[k][ty * 4];
            float4 b = *(const float4*)&Bs[k][tx * 4];
            acc[0][0] += a.x * b.x; acc[0][1] += a.x * b.y;
            acc[0][2] += a.x * b.z; acc[0][3] += a.x * b.w;
            acc[1][0] += a.y * b.x; acc[1][1] += a.y * b.y;
            acc[1][2] += a.y * b.z; acc[1][3] += a.y * b.w;
            acc[2][0] += a.z * b.x; acc[2][1] += a.z * b.y;
            acc[2][2] += a.z * b.z; acc[2][3] += a.z * b.w;
            acc[3][0] += a.w * b.x; acc[3][1] += a.w * b.y;
            acc[3][2] += a.w * b.z; acc[3][3] += a.w * b.w;
        }
        __syncthreads();
    }

    // ---- epilogue ----
    #pragma unroll
    for (int i = 0; i < 4; i++) {
        int r = rowBase + ty * 4 + i;
        if (r >= M) continue;
        float ivv = 0.f, dgv = 0.f;
        if (EPI == 2) { ivv = __ldg(&inv[r]); dgv = __ldg(&deg[r]); }
        #pragma unroll
        for (int j = 0; j < 4; j++) {
            int c = colBase + tx * 4 + j;
            if (c >= Nc) continue;
            float v = acc[i][j];
            if (EPI == 2) {
                v = v * ivv + (dgv > 0.f ? __ldg(&bias[c]) : 0.f);
            } else {
                v += __ldg(&bias[c]);
                if (EPI == 1) v = fmaxf(v, 0.f);
            }
            C[(size_t)r * Nc + c] = v;
        }
    }
}

extern "C" void kernel_launch(void* const* d_in, const int* in_sizes, int n_in,
                              void* d_out, int out_size) {
    const float* x_in   = (const float*)d_in[0];
    const float* eattr  = (const float*)d_in[1];
    const int*   eidx   = (const int*)  d_in[2];
    const float* node_W = (const float*)d_in[3];
    const float* node_b = (const float*)d_in[4];
    const float* edge_W = (const float*)d_in[5];
    const float* edge_b = (const float*)d_in[6];
    const float* W1     = (const float*)d_in[7];
    const float* b1     = (const float*)d_in[8];
    const float* W2     = (const float*)d_in[9];
    const float* b2     = (const float*)d_in[10];
    const float* eps    = (const float*)d_in[11];
    const float* lin_W  = (const float*)d_in[12];
    const float* lin_b  = (const float*)d_in[13];
    float* out = (float*)d_out;

    float *px, *ph1, *pagg, *peam, *pseg, *pdeg, *pinv;
    cudaGetSymbolAddress((void**)&px,   g_x);
    cudaGetSymbolAddress((void**)&ph1,  g_h1);
    cudaGetSymbolAddress((void**)&pagg, g_agg);
    cudaGetSymbolAddress((void**)&peam, g_eam);
    cudaGetSymbolAddress((void**)&pseg, g_seg);
    cudaGetSymbolAddress((void**)&pdeg, g_deg);
    cudaGetSymbolAddress((void**)&pinv, g_inv);

    // ---- graph preprocessing (once per call) ----
    zero_kernel<<<256, 256>>>(pdeg, NN);
    zero_kernel<<<2048, 256>>>(pseg, NN * IN_EDGE);
    deg_kernel<<<(EE + 255) / 256, 256>>>(eidx, pdeg);
    inv_kernel<<<(NN + 255) / 256, 256>>>(pdeg, pinv);
    seg_scatter_kernel<<<(EE * 16 + 255) / 256, 256>>>(eattr, eidx, pseg);

    dim3 gN128((NN + 63) / 64, HH / 64);       // Nc=128
    dim3 gN256((NN + 63) / 64, HH2 / 64);      // Nc=256
    dim3 gOut ((NN + 63) / 64, (OUTD + 63) / 64);

    // node encoder: g_x = x @ node_W + node_b
    gemm_kernel<0, 0><<<gN128, 256>>>(x_in, node_W, node_b, px,
                                      NN, 128, HH,
                                      nullptr, nullptr, nullptr, nullptr, nullptr, 0);
    // edge agg through encoder: g_eam = (seg @ edge_W)*inv_deg + [deg>0]*edge_b
    gemm_kernel<0, 2><<<gN128, 256>>>(pseg, edge_W, edge_b, peam,
                                      NN, IN_EDGE, HH,
                                      nullptr, nullptr, pinv, pdeg, nullptr, 0);

    for (int l = 0; l < 3; l++) {
        zero_kernel<<<2048, 256>>>(pagg, NN * HH);
        x_scatter_kernel<<<EE * 32 / 256, 256>>>(eidx, px, pagg);
        // h1 = relu( ((1+eps)*x + agg*inv + eam) @ W1[l] + b1[l] )
        gemm_kernel<1, 1><<<gN256, 256>>>(px, W1 + (size_t)l * HH * HH2,
                                          b1 + (size_t)l * HH2, ph1,
                                          NN, HH, HH2,
                                          pagg, peam, pinv, nullptr, eps, l);
        // x = relu( h1 @ W2[l] + b2[l] )
        gemm_kernel<0, 1><<<gN128, 256>>>(ph1, W2 + (size_t)l * HH2 * HH,
                                          b2 + (size_t)l * HH, px,
                                          NN, HH2, HH,
                                          nullptr, nullptr, nullptr, nullptr, nullptr, 0);
    }

    // head: out = x @ lin_W + lin_b
    gemm_kernel<0, 0><<<gOut, 256>>>(px, lin_W, lin_b, out,
                                     NN, HH, OUTD,
                                     nullptr, nullptr, nullptr, nullptr, nullptr, 0);
}

// round 3
// speedup vs baseline: 1.5390x; 1.5390x over previous
#include <cuda_runtime.h>
#include <cuda_bf16.h>
#include <cstdint>

#define NN     50000
#define EE     625000
#define IN_EDGE 64
#define HH     128
#define HH2    256
#define OUTD   112
#define TILES_M 391   // ceil(50000/128)

// ---------------- scratch (device globals; no allocation allowed) ----------
__device__ float g_x  [NN * HH];
__device__ float g_h1 [NN * HH2];
__device__ float g_agg[NN * HH];
__device__ float g_eam[NN * HH];
__device__ float g_seg[NN * IN_EDGE];
__device__ float g_deg[NN];
__device__ float g_inv[NN];

// pre-split transposed weights, layout [N][K] bf16, hi/lo
//   node  [128][128] @ 0        edge [128][64] @ 16384
//   W1[l] [256][128] @ 24576+l*32768   W2[l] [128][256] @ 122880+l*32768
//   lin   [112][128] @ 221184
__device__ __nv_bfloat16 g_whi[235520];
__device__ __nv_bfloat16 g_wlo[235520];

// ---------------------------------------------------------------------------
__device__ __forceinline__ uint32_t smem_u32(const void* p) {
    uint32_t a;
    asm("{ .reg .u64 t; cvta.to.shared.u64 t, %1; cvt.u32.u64 %0, t; }"
        : "=r"(a) : "l"(p));
    return a;
}
__device__ __forceinline__ void cp16(uint32_t dst, const void* src) {
    asm volatile("cp.async.cg.shared.global [%0], [%1], 16;"
                 :: "r"(dst), "l"(src) : "memory");
}
__device__ __forceinline__ void zero16(uint32_t dst) {
    asm volatile("st.shared.v4.b32 [%0], {%1,%1,%1,%1};" :: "r"(dst), "r"(0) : "memory");
}
__device__ __forceinline__ void ldsm4(uint32_t* r, uint32_t addr) {
    asm volatile("ldmatrix.sync.aligned.m8n8.x4.shared.b16 {%0,%1,%2,%3}, [%4];"
                 : "=r"(r[0]), "=r"(r[1]), "=r"(r[2]), "=r"(r[3]) : "r"(addr));
}
__device__ __forceinline__ void mma16816(float* d, const uint32_t* a, const uint32_t* b) {
    asm volatile("mma.sync.aligned.m16n8k16.row.col.f32.bf16.bf16.f32 "
                 "{%0,%1,%2,%3}, {%4,%5,%6,%7}, {%8,%9}, {%0,%1,%2,%3};"
                 : "+f"(d[0]), "+f"(d[1]), "+f"(d[2]), "+f"(d[3])
                 : "r"(a[0]), "r"(a[1]), "r"(a[2]), "r"(a[3]), "r"(b[0]), "r"(b[1]));
}
__device__ __forceinline__ void red_add_v4(float* addr, float4 v) {
    asm volatile("red.global.add.v4.f32 [%0], {%1,%2,%3,%4};"
                 :: "l"(addr), "f"(v.x), "f"(v.y), "f"(v.z), "f"(v.w) : "memory");
}

// ---------------------------------------------------------------------------
// graph preprocessing
// ---------------------------------------------------------------------------
__global__ void zero_kernel(float* __restrict__ p, int n) {
    int i = blockIdx.x * blockDim.x + threadIdx.x;
    int stride = gridDim.x * blockDim.x;
    for (; i < n; i += stride) p[i] = 0.f;
}
__global__ void deg_kernel(const int* __restrict__ ei, float* __restrict__ deg) {
    int e = blockIdx.x * blockDim.x + threadIdx.x;
    if (e < EE) atomicAdd(&deg[ei[EE + e]], 1.0f);
}
__global__ void inv_kernel(const float* __restrict__ deg, float* __restrict__ inv) {
    int i = blockIdx.x * blockDim.x + threadIdx.x;
    if (i < NN) inv[i] = 1.0f / fmaxf(deg[i], 1.0f);
}
__global__ void seg_scatter_kernel(const float* __restrict__ ea,
                                   const int* __restrict__ ei,
                                   float* __restrict__ seg) {
    int gid = blockIdx.x * blockDim.x + threadIdx.x;
    if (gid >= EE * 16) return;
    int e = gid >> 4, g = gid & 15;
    int dst = __ldg(&ei[EE + e]);
    float4 v = __ldg(((const float4*)ea) + (size_t)e * 16 + g);
    red_add_v4(seg + (size_t)dst * IN_EDGE + g * 4, v);
}
__global__ void x_scatter_kernel(const int* __restrict__ ei,
                                 const float* __restrict__ x,
                                 float* __restrict__ agg) {
    int gid = blockIdx.x * blockDim.x + threadIdx.x;
    int e = gid >> 5;
    int lane = threadIdx.x & 31;
    int src = 0, dst = 0;
    if (lane == 0) { src = __ldg(&ei[e]); dst = __ldg(&ei[EE + e]); }
    src = __shfl_sync(0xffffffffu, src, 0);
    dst = __shfl_sync(0xffffffffu, dst, 0);
    float4 v = __ldg(((const float4*)x) + (size_t)src * 32 + lane);
    red_add_v4(agg + (size_t)dst * HH + lane * 4, v);
}

// all weights: W[K][Nc] fp32 -> [N][K] bf16 hi/lo (transpose + split), fused
__global__ void wprep_all(const float* __restrict__ node_W, const float* __restrict__ edge_W,
                          const float* __restrict__ W1, const float* __restrict__ W2,
                          const float* __restrict__ lin_W,
                          __nv_bfloat16* __restrict__ hi, __nv_bfloat16* __restrict__ lo) {
    int i = blockIdx.x * blockDim.x + threadIdx.x;
    if (i >= 235520) return;
    const float* src; int K, Nc, idx;
    if (i < 16384)       { src = node_W;                 K = 128; Nc = 128; idx = i; }
    else if (i < 24576)  { src = edge_W;                 K =  64; Nc = 128; idx = i - 16384; }
    else if (i < 122880) { int j = i - 24576;  src = W1 + (j / 32768) * 32768; K = 128; Nc = 256; idx = j % 32768; }
    else if (i < 221184) { int j = i - 122880; src = W2 + (j / 32768) * 32768; K = 256; Nc = 128; idx = j % 32768; }
    else                 { src = lin_W;                  K = 128; Nc = 112; idx = i - 221184; }
    int n = idx / K, k = idx % K;
    float v = __ldg(&src[(size_t)k * Nc + n]);
    __nv_bfloat16 h = __float2bfloat16(v);
    hi[i] = h;
    lo[i] = __float2bfloat16(v - __bfloat162float(h));
}

// ---------------------------------------------------------------------------
// split-bf16 mma.sync GEMM: C[NN,Nc] = epi( A_eff[NN,KTOT] @ B[KTOT,Nc] )
// B pre-transposed+split [Nc][KTOT] bf16 hi/lo. Block tile 128x64, BK=64 slab.
// 8 warps, warp tile 32x32 (warp_m = wid&3, warp_n = wid>>2).
// MODEA 1: A_eff = (1+eps)*x + agg*inv + eam.  EPI: 0 bias, 1 relu, 2 edge-mean.
// smem rows padded to 144B -> conflict-free ldmatrix phases.
// ---------------------------------------------------------------------------
#define ROWB 144
template <int KTOT, int MODEA, int EPI>
__global__ void __launch_bounds__(256, 2)
gemm_mma(const float* __restrict__ A,
         const __nv_bfloat16* __restrict__ Bhi, const __nv_bfloat16* __restrict__ Blo,
         const float* __restrict__ bias, float* __restrict__ C, int Nc,
         const float* __restrict__ agg, const float* __restrict__ eam,
         const float* __restrict__ inv, const float* __restrict__ deg,
         const float* __restrict__ eps_p, int layer) {
    extern __shared__ char smem[];
    const uint32_t sb  = smem_u32(smem);
    const uint32_t sAh = sb,          sAl = sb + 18432;
    const uint32_t sBh = sb + 36864,  sBl = sb + 46080;

    const int tid  = threadIdx.x;
    const int lane = tid & 31;
    const int wid  = tid >> 5;
    const int wm   = wid & 3;          // row group of 32
    const int wn   = wid >> 2;         // col group of 32
    const int rowBase = blockIdx.x * 128;
    const int colBase = blockIdx.y * 64;

    float acc[2][4][4];
    #pragma unroll
    for (int a = 0; a < 2; a++)
        #pragma unroll
        for (int b = 0; b < 4; b++)
            #pragma unroll
            for (int c = 0; c < 4; c++) acc[a][b][c] = 0.f;

    float epsv = 0.f;
    if (MODEA == 1) epsv = 1.f + __ldg(&eps_p[layer]);

    // precomputed ldmatrix lane offsets
    const uint32_t aRow  = (uint32_t)(lane & 15);
    const uint32_t aKoff = (uint32_t)((lane >> 4) << 3);
    const uint32_t bRow  = (uint32_t)((lane & 7) + ((lane >> 4) << 3));
    const uint32_t bKoff = (uint32_t)(((lane >> 3) & 1) << 3);

    for (int kb = 0; kb < KTOT; kb += 64) {
        if (kb) __syncthreads();

        // ---- B slab via cp.async (64 n-rows x 64 k bf16, hi+lo) ----
        #pragma unroll
        for (int i = 0; i < 2; i++) {
            int f = tid + i * 256;          // 0..511
            int nrow = f >> 3, chunk = f & 7;
            uint32_t dh = sBh + nrow * ROWB + chunk * 16;
            uint32_t dl = sBl + nrow * ROWB + chunk * 16;
            int gn = colBase + nrow;
            if (gn < Nc) {
                size_t off = (size_t)gn * KTOT + kb + chunk * 8;
                cp16(dh, Bhi + off);
                cp16(dl, Blo + off);
            } else { zero16(dh); zero16(dl); }
        }
        asm volatile("cp.async.commit_group;" ::: "memory");

        // ---- A slab: 128 rows x 64 k fp32 -> split bf16 hi/lo ----
        #pragma unroll
        for (int i = 0; i < 8; i++) {
            int f = tid + i * 256;          // 0..2047
            int row = f >> 4;
            int c4  = f & 15;               // float4 index within 64-k row
            int gr = rowBase + row;
            float4 v = make_float4(0.f, 0.f, 0.f, 0.f);
            if (gr < NN) {
                size_t off = (size_t)gr * KTOT + kb + c4 * 4;
                v = __ldg((const float4*)(A + off));
                if (MODEA == 1) {
                    float4 ag = __ldg((const float4*)(agg + off));
                    float4 em = __ldg((const float4*)(eam + off));
                    float iv  = __ldg(&inv[gr]);
                    v.x = epsv * v.x + ag.x * iv + em.x;
                    v.y = epsv * v.y + ag.y * iv + em.y;
                    v.z = epsv * v.z + ag.z * iv + em.z;
                    v.w = epsv * v.w + ag.w * iv + em.w;
                }
            }
            __nv_bfloat16 hx = __float2bfloat16(v.x), hy = __float2bfloat16(v.y);
            __nv_bfloat16 hz = __float2bfloat16(v.z), hw = __float2bfloat16(v.w);
            __nv_bfloat162 h01 = __halves2bfloat162(hx, hy);
            __nv_bfloat162 h23 = __halves2bfloat162(hz, hw);
            __nv_bfloat162 l01 = __halves2bfloat162(
                __float2bfloat16(v.x - __bfloat162float(hx)),
                __float2bfloat16(v.y - __bfloat162float(hy)));
            __nv_bfloat162 l23 = __halves2bfloat162(
                __float2bfloat16(v.z - __bfloat162float(hz)),
                __float2bfloat16(v.w - __bfloat162float(hw)));
            uint32_t addr = row * ROWB + c4 * 8;
            asm volatile("st.shared.v2.b32 [%0], {%1,%2};"
                         :: "r"(sAh + addr), "r"(*(uint32_t*)&h01), "r"(*(uint32_t*)&h23) : "memory");
            asm volatile("st.shared.v2.b32 [%0], {%1,%2};"
                         :: "r"(sAl + addr), "r"(*(uint32_t*)&l01), "r"(*(uint32_t*)&l23) : "memory");
        }
        asm volatile("cp.async.wait_group 0;" ::: "memory");
        __syncthreads();

        // ---- 4 k16 steps of mma ----
        #pragma unroll
        for (int ks = 0; ks < 4; ks++) {
            uint32_t ah[2][4], al[2][4], bh[4][2], bl[4][2];
            #pragma unroll
            for (int mi = 0; mi < 2; mi++) {
                uint32_t off = (wm * 32 + mi * 16 + aRow) * ROWB + (ks * 16 + aKoff) * 2;
                ldsm4(ah[mi], sAh + off);
                ldsm4(al[mi], sAl + off);
            }
            #pragma unroll
            for (int pr = 0; pr < 2; pr++) {
                uint32_t off = (wn * 32 + pr * 16 + bRow) * ROWB + (ks * 16 + bKoff) * 2;
                uint32_t t[4];
                ldsm4(t, sBh + off);
                bh[pr*2][0] = t[0]; bh[pr*2][1] = t[1];
                bh[pr*2+1][0] = t[2]; bh[pr*2+1][1] = t[3];
                ldsm4(t, sBl + off);
                bl[pr*2][0] = t[0]; bl[pr*2][1] = t[1];
                bl[pr*2+1][0] = t[2]; bl[pr*2+1][1] = t[3];
            }
            #pragma unroll
            for (int mi = 0; mi < 2; mi++)
                #pragma unroll
                for (int ni = 0; ni < 4; ni++) {
                    mma16816(acc[mi][ni], ah[mi], bh[ni]);
                    mma16816(acc[mi][ni], ah[mi], bl[ni]);
                    mma16816(acc[mi][ni], al[mi], bh[ni]);
                }
        }
    }

    // ---- epilogue ----
    const int group = lane >> 2;
    const int qc    = (lane & 3) * 2;
    #pragma unroll
    for (int mi = 0; mi < 2; mi++) {
        int r0 = rowBase + wm * 32 + mi * 16 + group;
        int r1 = r0 + 8;
        float iv0 = 0.f, m0 = 0.f, iv1 = 0.f, m1 = 0.f;
        if (EPI == 2) {
            if (r0 < NN) { iv0 = __ldg(&inv[r0]); m0 = (__ldg(&deg[r0]) > 0.f) ? 1.f : 0.f; }
            if (r1 < NN) { iv1 = __ldg(&inv[r1]); m1 = (__ldg(&deg[r1]) > 0.f) ? 1.f : 0.f; }
        }
        #pragma unroll
        for (int ni = 0; ni < 4; ni++) {
            int c = colBase + wn * 32 + ni * 8 + qc;
            if (c >= Nc) continue;
            float b0 = __ldg(&bias[c]), b1 = __ldg(&bias[c + 1]);
            float2 v0, v1;
            if (EPI == 2) {
                v0.x = acc[mi][ni][0] * iv0 + m0 * b0;
                v0.y = acc[mi][ni][1] * iv0 + m0 * b1;
                v1.x = acc[mi][ni][2] * iv1 + m1 * b0;
                v1.y = acc[mi][ni][3] * iv1 + m1 * b1;
            } else {
                v0.x = acc[mi][ni][0] + b0; v0.y = acc[mi][ni][1] + b1;
                v1.x = acc[mi][ni][2] + b0; v1.y = acc[mi][ni][3] + b1;
                if (EPI == 1) {
                    v0.x = fmaxf(v0.x, 0.f); v0.y = fmaxf(v0.y, 0.f);
                    v1.x = fmaxf(v1.x, 0.f); v1.y = fmaxf(v1.y, 0.f);
                }
            }
            if (r0 < NN) *(float2*)(C + (size_t)r0 * Nc + c) = v0;
            if (r1 < NN) *(float2*)(C + (size_t)r1 * Nc + c) = v1;
        }
    }
}

// ---------------------------------------------------------------------------
extern "C" void kernel_launch(void* const* d_in, const int* in_sizes, int n_in,
                              void* d_out, int out_size) {
    const float* x_in   = (const float*)d_in[0];
    const float* eattr  = (const float*)d_in[1];
    const int*   eidx   = (const int*)  d_in[2];
    const float* node_W = (const float*)d_in[3];
    const float* node_b = (const float*)d_in[4];
    const float* edge_W = (const float*)d_in[5];
    const float* edge_b = (const float*)d_in[6];
    const float* W1     = (const float*)d_in[7];
    const float* b1     = (const float*)d_in[8];
    const float* W2     = (const float*)d_in[9];
    const float* b2     = (const float*)d_in[10];
    const float* eps    = (const float*)d_in[11];
    const float* lin_W  = (const float*)d_in[12];
    const float* lin_b  = (const float*)d_in[13];
    float* out = (float*)d_out;

    float *px, *ph1, *pagg, *peam, *pseg, *pdeg, *pinv;
    __nv_bfloat16 *pwh, *pwl;
    cudaGetSymbolAddress((void**)&px,   g_x);
    cudaGetSymbolAddress((void**)&ph1,  g_h1);
    cudaGetSymbolAddress((void**)&pagg, g_agg);
    cudaGetSymbolAddress((void**)&peam, g_eam);
    cudaGetSymbolAddress((void**)&pseg, g_seg);
    cudaGetSymbolAddress((void**)&pdeg, g_deg);
    cudaGetSymbolAddress((void**)&pinv, g_inv);
    cudaGetSymbolAddress((void**)&pwh,  g_whi);
    cudaGetSymbolAddress((void**)&pwl,  g_wlo);

    constexpr int SMEM = 55296;
    auto setsm = [](const void* f) {
        cudaFuncSetAttribute(f, cudaFuncAttributeMaxDynamicSharedMemorySize, SMEM);
    };
    setsm((const void*)gemm_mma<128, 0, 0>);
    setsm((const void*)gemm_mma< 64, 0, 2>);
    setsm((const void*)gemm_mma<128, 1, 1>);
    setsm((const void*)gemm_mma<256, 0, 1>);

    // ---- weight prep (fused) ----
    wprep_all<<<920, 256>>>(node_W, edge_W, W1, W2, lin_W, pwh, pwl);

    // ---- graph preprocessing ----
    zero_kernel<<<256, 256>>>(pdeg, NN);
    zero_kernel<<<2048, 256>>>(pseg, NN * IN_EDGE);
    deg_kernel<<<(EE + 255) / 256, 256>>>(eidx, pdeg);
    inv_kernel<<<(NN + 255) / 256, 256>>>(pdeg, pinv);
    seg_scatter_kernel<<<(EE * 16 + 255) / 256, 256>>>(eattr, eidx, pseg);

    dim3 g2(TILES_M, 2), g4(TILES_M, 4);

    // node encoder: g_x = x @ node_W + node_b
    gemm_mma<128, 0, 0><<<g2, 256, SMEM>>>(x_in, pwh, pwl, node_b, px, HH,
        nullptr, nullptr, nullptr, nullptr, nullptr, 0);
    // edge agg through encoder: g_eam = (seg @ edge_W)*inv + [deg>0]*edge_b
    gemm_mma<64, 0, 2><<<g2, 256, SMEM>>>(pseg, pwh + 16384, pwl + 16384,
        edge_b, peam, HH, nullptr, nullptr, pinv, pdeg, nullptr, 0);

    for (int l = 0; l < 3; l++) {
        zero_kernel<<<2048, 256>>>(pagg, NN * HH);
        x_scatter_kernel<<<EE * 32 / 256, 256>>>(eidx, px, pagg);
        // h1 = relu( ((1+eps)x + agg*inv + eam) @ W1[l] + b1[l] )
        gemm_mma<128, 1, 1><<<g4, 256, SMEM>>>(px,
            pwh + 24576 + l * 32768, pwl + 24576 + l * 32768,
            b1 + (size_t)l * HH2, ph1, HH2, pagg, peam, pinv, nullptr, eps, l);
        // x = relu( h1 @ W2[l] + b2[l] )
        gemm_mma<256, 0, 1><<<g2, 256, SMEM>>>(ph1,
            pwh + 122880 + l * 32768, pwl + 122880 + l * 32768,
            b2 + (size_t)l * HH, px, HH, nullptr, nullptr, nullptr, nullptr, nullptr, 0);
    }

    // head: out = x @ lin_W + lin_b
    gemm_mma<128, 0, 0><<<g2, 256, SMEM>>>(px, pwh + 221184, pwl + 221184,
        lin_b, out, OUTD, nullptr, nullptr, nullptr, nullptr, nullptr, 0);
}

// round 4
// speedup vs baseline: 1.8434x; 1.1977x over previous
#include <cuda_runtime.h>
#include <cuda_bf16.h>
#include <cstdint>

#define NN     50000
#define EE     625000
#define IN_EDGE 64
#define HH     128
#define HH2    256
#define OUTD   112
#define TILES_M 391   // ceil(50000/128)

// ---------------- scratch (device globals; no allocation allowed) ----------
__device__ __align__(16) float g_x  [NN * HH];
__device__ __align__(16) float g_agg[NN * HH];
__device__ __align__(16) float g_eam[NN * HH];
__device__ __align__(16) float g_seg[NN * IN_EDGE];
__device__ float g_deg[NN];
__device__ float g_inv[NN];

// split activations (bf16 hi/lo)
__device__ __align__(16) __nv_bfloat16 g_ch [NN * HH];    // combined, W1 input
__device__ __align__(16) __nv_bfloat16 g_cl [NN * HH];
__device__ __align__(16) __nv_bfloat16 g_h1h[NN * HH2];   // W1 output, W2 input
__device__ __align__(16) __nv_bfloat16 g_h1l[NN * HH2];
__device__ __align__(16) __nv_bfloat16 g_xh [NN * HH];    // W2 output, head input
__device__ __align__(16) __nv_bfloat16 g_xl [NN * HH];

// pre-split transposed weights, layout [N][K] bf16, hi/lo
//   node  [128][128] @ 0        edge [128][64] @ 16384
//   W1[l] [256][128] @ 24576+l*32768   W2[l] [128][256] @ 122880+l*32768
//   lin   [112][128] @ 221184
__device__ __align__(16) __nv_bfloat16 g_whi[235520];
__device__ __align__(16) __nv_bfloat16 g_wlo[235520];

// ---------------------------------------------------------------------------
__device__ __forceinline__ uint32_t smem_u32(const void* p) {
    uint32_t a;
    asm("{ .reg .u64 t; cvta.to.shared.u64 t, %1; cvt.u32.u64 %0, t; }"
        : "=r"(a) : "l"(p));
    return a;
}
__device__ __forceinline__ void cp16(uint32_t dst, const void* src) {
    asm volatile("cp.async.cg.shared.global [%0], [%1], 16;"
                 :: "r"(dst), "l"(src) : "memory");
}
__device__ __forceinline__ void zero16(uint32_t dst) {
    asm volatile("st.shared.v4.b32 [%0], {%1,%1,%1,%1};" :: "r"(dst), "r"(0) : "memory");
}
__device__ __forceinline__ void ldsm4(uint32_t* r, uint32_t addr) {
    asm volatile("ldmatrix.sync.aligned.m8n8.x4.shared.b16 {%0,%1,%2,%3}, [%4];"
                 : "=r"(r[0]), "=r"(r[1]), "=r"(r[2]), "=r"(r[3]) : "r"(addr));
}
__device__ __forceinline__ void mma16816(float* d, const uint32_t* a, const uint32_t* b) {
    asm volatile("mma.sync.aligned.m16n8k16.row.col.f32.bf16.bf16.f32 "
                 "{%0,%1,%2,%3}, {%4,%5,%6,%7}, {%8,%9}, {%0,%1,%2,%3};"
                 : "+f"(d[0]), "+f"(d[1]), "+f"(d[2]), "+f"(d[3])
                 : "r"(a[0]), "r"(a[1]), "r"(a[2]), "r"(a[3]), "r"(b[0]), "r"(b[1]));
}
__device__ __forceinline__ void red_add_v4(float* addr, float4 v) {
    asm volatile("red.global.add.v4.f32 [%0], {%1,%2,%3,%4};"
                 :: "l"(addr), "f"(v.x), "f"(v.y), "f"(v.z), "f"(v.w) : "memory");
}
__device__ __forceinline__ void split2(float a, float b, uint32_t& hi, uint32_t& lo) {
    __nv_bfloat16 ha = __float2bfloat16(a), hb = __float2bfloat16(b);
    __nv_bfloat162 h = __halves2bfloat162(ha, hb);
    __nv_bfloat162 l = __halves2bfloat162(
        __float2bfloat16(a - __bfloat162float(ha)),
        __float2bfloat16(b - __bfloat162float(hb)));
    hi = *(uint32_t*)&h; lo = *(uint32_t*)&l;
}

// ---------------------------------------------------------------------------
// graph preprocessing
// ---------------------------------------------------------------------------
__global__ void zero_kernel(float* __restrict__ p, int n) {
    int i = blockIdx.x * blockDim.x + threadIdx.x;
    int stride = gridDim.x * blockDim.x;
    for (; i < n; i += stride) p[i] = 0.f;
}
__global__ void deg_kernel(const int* __restrict__ ei, float* __restrict__ deg) {
    int e = blockIdx.x * blockDim.x + threadIdx.x;
    if (e < EE) atomicAdd(&deg[ei[EE + e]], 1.0f);
}
__global__ void inv_kernel(const float* __restrict__ deg, float* __restrict__ inv) {
    int i = blockIdx.x * blockDim.x + threadIdx.x;
    if (i < NN) inv[i] = 1.0f / fmaxf(deg[i], 1.0f);
}
__global__ void seg_scatter_kernel(const float* __restrict__ ea,
                                   const int* __restrict__ ei,
                                   float* __restrict__ seg) {
    int gid = blockIdx.x * blockDim.x + threadIdx.x;
    if (gid >= EE * 16) return;
    int e = gid >> 4, g = gid & 15;
    int dst = __ldg(&ei[EE + e]);
    float4 v = __ldg(((const float4*)ea) + (size_t)e * 16 + g);
    red_add_v4(seg + (size_t)dst * IN_EDGE + g * 4, v);
}
__global__ void x_scatter_kernel(const int* __restrict__ ei,
                                 const float* __restrict__ x,
                                 float* __restrict__ agg) {
    int gid = blockIdx.x * blockDim.x + threadIdx.x;
    int e = gid >> 5;
    int lane = threadIdx.x & 31;
    int src = 0, dst = 0;
    if (lane == 0) { src = __ldg(&ei[e]); dst = __ldg(&ei[EE + e]); }
    src = __shfl_sync(0xffffffffu, src, 0);
    dst = __shfl_sync(0xffffffffu, dst, 0);
    float4 v = __ldg(((const float4*)x) + (size_t)src * 32 + lane);
    red_add_v4(agg + (size_t)dst * HH + lane * 4, v);
}

// combine + split: c = (1+eps)x + agg*inv + eam -> ch/cl bf16
__global__ void combine_split(const float* __restrict__ x, const float* __restrict__ agg,
                              const float* __restrict__ eam, const float* __restrict__ inv,
                              const float* __restrict__ eps_p, int layer,
                              __nv_bfloat16* __restrict__ ch, __nv_bfloat16* __restrict__ cl) {
    int i = blockIdx.x * blockDim.x + threadIdx.x;   // float4 index
    if (i >= NN * 32) return;
    int r = i >> 5;
    float epsv = 1.f + __ldg(&eps_p[layer]);
    float iv = __ldg(&inv[r]);
    float4 xv = __ldg((const float4*)x + i);
    float4 ag = __ldg((const float4*)agg + i);
    float4 em = __ldg((const float4*)eam + i);
    float4 v;
    v.x = epsv * xv.x + ag.x * iv + em.x;
    v.y = epsv * xv.y + ag.y * iv + em.y;
    v.z = epsv * xv.z + ag.z * iv + em.z;
    v.w = epsv * xv.w + ag.w * iv + em.w;
    uint2 h, l;
    split2(v.x, v.y, h.x, l.x);
    split2(v.z, v.w, h.y, l.y);
    *(uint2*)(ch + (size_t)i * 4) = h;
    *(uint2*)(cl + (size_t)i * 4) = l;
}

// all weights: W[K][Nc] fp32 -> [N][K] bf16 hi/lo (transpose + split), fused
__global__ void wprep_all(const float* __restrict__ node_W, const float* __restrict__ edge_W,
                          const float* __restrict__ W1, const float* __restrict__ W2,
                          const float* __restrict__ lin_W,
                          __nv_bfloat16* __restrict__ hi, __nv_bfloat16* __restrict__ lo) {
    int i = blockIdx.x * blockDim.x + threadIdx.x;
    if (i >= 235520) return;
    const float* src; int K, Nc, idx;
    if (i < 16384)       { src = node_W;                 K = 128; Nc = 128; idx = i; }
    else if (i < 24576)  { src = edge_W;                 K =  64; Nc = 128; idx = i - 16384; }
    else if (i < 122880) { int j = i - 24576;  src = W1 + (j / 32768) * 32768; K = 128; Nc = 256; idx = j % 32768; }
    else if (i < 221184) { int j = i - 122880; src = W2 + (j / 32768) * 32768; K = 256; Nc = 128; idx = j % 32768; }
    else                 { src = lin_W;                  K = 128; Nc = 112; idx = i - 221184; }
    int n = idx / K, k = idx % K;
    float v = __ldg(&src[(size_t)k * Nc + n]);
    __nv_bfloat16 h = __float2bfloat16(v);
    hi[i] = h;
    lo[i] = __float2bfloat16(v - __bfloat162float(h));
}

// ---------------------------------------------------------------------------
// Round-3 style GEMM with fp32-A conversion loader (node & edge encoders only).
// EPI: 0 = +bias; 2 = *inv + [deg>0]*bias
// ---------------------------------------------------------------------------
#define ROWB 144
template <int KTOT, int EPI>
__global__ void __launch_bounds__(256, 2)
gemm_f32a(const float* __restrict__ A,
          const __nv_bfloat16* __restrict__ Bhi, const __nv_bfloat16* __restrict__ Blo,
          const float* __restrict__ bias, float* __restrict__ C, int Nc,
          const float* __restrict__ inv, const float* __restrict__ deg) {
    extern __shared__ char smem[];
    const uint32_t sb  = smem_u32(smem);
    const uint32_t sAh = sb,          sAl = sb + 18432;
    const uint32_t sBh = sb + 36864,  sBl = sb + 46080;

    const int tid  = threadIdx.x;
    const int lane = tid & 31;
    const int wid  = tid >> 5;
    const int wm   = wid & 3;
    const int wn   = wid >> 2;
    const int rowBase = blockIdx.x * 128;
    const int colBase = blockIdx.y * 64;

    float acc[2][4][4];
    #pragma unroll
    for (int a = 0; a < 2; a++)
        #pragma unroll
        for (int b = 0; b < 4; b++)
            #pragma unroll
            for (int c = 0; c < 4; c++) acc[a][b][c] = 0.f;

    const uint32_t aRow  = (uint32_t)(lane & 15);
    const uint32_t aKoff = (uint32_t)((lane >> 4) << 3);
    const uint32_t bRow  = (uint32_t)((lane & 7) + ((lane >> 4) << 3));
    const uint32_t bKoff = (uint32_t)(((lane >> 3) & 1) << 3);

    for (int kb = 0; kb < KTOT; kb += 64) {
        if (kb) __syncthreads();
        #pragma unroll
        for (int i = 0; i < 2; i++) {
            int f = tid + i * 256;
            int nrow = f >> 3, chunk = f & 7;
            uint32_t dh = sBh + nrow * ROWB + chunk * 16;
            uint32_t dl = sBl + nrow * ROWB + chunk * 16;
            int gn = colBase + nrow;
            if (gn < Nc) {
                size_t off = (size_t)gn * KTOT + kb + chunk * 8;
                cp16(dh, Bhi + off);
                cp16(dl, Blo + off);
            } else { zero16(dh); zero16(dl); }
        }
        asm volatile("cp.async.commit_group;" ::: "memory");

        #pragma unroll
        for (int i = 0; i < 8; i++) {
            int f = tid + i * 256;
            int row = f >> 4;
            int c4  = f & 15;
            int gr = rowBase + row;
            float4 v = make_float4(0.f, 0.f, 0.f, 0.f);
            if (gr < NN) v = __ldg((const float4*)(A + (size_t)gr * KTOT + kb + c4 * 4));
            uint32_t h01, h23, l01, l23;
            split2(v.x, v.y, h01, l01);
            split2(v.z, v.w, h23, l23);
            uint32_t addr = row * ROWB + c4 * 8;
            asm volatile("st.shared.v2.b32 [%0], {%1,%2};"
                         :: "r"(sAh + addr), "r"(h01), "r"(h23) : "memory");
            asm volatile("st.shared.v2.b32 [%0], {%1,%2};"
                         :: "r"(sAl + addr), "r"(l01), "r"(l23) : "memory");
        }
        asm volatile("cp.async.wait_group 0;" ::: "memory");
        __syncthreads();

        #pragma unroll
        for (int ks = 0; ks < 4; ks++) {
            uint32_t ah[2][4], al[2][4], bh[4][2], bl[4][2];
            #pragma unroll
            for (int mi = 0; mi < 2; mi++) {
                uint32_t off = (wm * 32 + mi * 16 + aRow) * ROWB + (ks * 16 + aKoff) * 2;
                ldsm4(ah[mi], sAh + off);
                ldsm4(al[mi], sAl + off);
            }
            #pragma unroll
            for (int pr = 0; pr < 2; pr++) {
                uint32_t off = (wn * 32 + pr * 16 + bRow) * ROWB + (ks * 16 + bKoff) * 2;
                uint32_t t[4];
                ldsm4(t, sBh + off);
                bh[pr*2][0] = t[0]; bh[pr*2][1] = t[1];
                bh[pr*2+1][0] = t[2]; bh[pr*2+1][1] = t[3];
                ldsm4(t, sBl + off);
                bl[pr*2][0] = t[0]; bl[pr*2][1] = t[1];
                bl[pr*2+1][0] = t[2]; bl[pr*2+1][1] = t[3];
            }
            #pragma unroll
            for (int mi = 0; mi < 2; mi++)
                #pragma unroll
                for (int ni = 0; ni < 4; ni++) {
                    mma16816(acc[mi][ni], ah[mi], bh[ni]);
                    mma16816(acc[mi][ni], ah[mi], bl[ni]);
                    mma16816(acc[mi][ni], al[mi], bh[ni]);
                }
        }
    }

    const int group = lane >> 2;
    const int qc    = (lane & 3) * 2;
    #pragma unroll
    for (int mi = 0; mi < 2; mi++) {
        int r0 = rowBase + wm * 32 + mi * 16 + group;
        int r1 = r0 + 8;
        float iv0 = 0.f, m0 = 0.f, iv1 = 0.f, m1 = 0.f;
        if (EPI == 2) {
            if (r0 < NN) { iv0 = __ldg(&inv[r0]); m0 = (__ldg(&deg[r0]) > 0.f) ? 1.f : 0.f; }
            if (r1 < NN) { iv1 = __ldg(&inv[r1]); m1 = (__ldg(&deg[r1]) > 0.f) ? 1.f : 0.f; }
        }
        #pragma unroll
        for (int ni = 0; ni < 4; ni++) {
            int c = colBase + wn * 32 + ni * 8 + qc;
            if (c >= Nc) continue;
            float b0 = __ldg(&bias[c]), b1 = __ldg(&bias[c + 1]);
            float2 v0, v1;
            if (EPI == 2) {
                v0.x = acc[mi][ni][0] * iv0 + m0 * b0;
                v0.y = acc[mi][ni][1] * iv0 + m0 * b1;
                v1.x = acc[mi][ni][2] * iv1 + m1 * b0;
                v1.y = acc[mi][ni][3] * iv1 + m1 * b1;
            } else {
                v0.x = acc[mi][ni][0] + b0; v0.y = acc[mi][ni][1] + b1;
                v1.x = acc[mi][ni][2] + b0; v1.y = acc[mi][ni][3] + b1;
            }
            if (r0 < NN) *(float2*)(C + (size_t)r0 * Nc + c) = v0;
            if (r1 < NN) *(float2*)(C + (size_t)r1 * Nc + c) = v1;
        }
    }
}

// ---------------------------------------------------------------------------
// Pipelined split-bf16 GEMM, A pre-split: C = epi( (Ah+Al) @ (Bh+Bl) )
// XOR-swizzled 128B rows, 2-stage cp.async pipeline, 2 CTAs/SM.
// EPI: 0 = +bias, 1 = relu(+bias)
// OUTMODE: 0 = fp32 only; 1 = bf16 split only; 2 = fp32 + bf16 split
// ---------------------------------------------------------------------------
template <int KTOT, int EPI, int OUTMODE>
__global__ void __launch_bounds__(256, 2)
gemm_bf16(const __nv_bfloat16* __restrict__ Ah, const __nv_bfloat16* __restrict__ Al,
          const __nv_bfloat16* __restrict__ Bhi, const __nv_bfloat16* __restrict__ Blo,
          const float* __restrict__ bias, float* __restrict__ Cf,
          __nv_bfloat16* __restrict__ Ch, __nv_bfloat16* __restrict__ Cl, int Nc) {
    constexpr int CHUNKS = KTOT / 64;
    constexpr int STG = 49152;   // Ah 16K | Al 16K | Bh 8K | Bl 8K
    extern __shared__ char smem[];
    const uint32_t sb = smem_u32(smem);

    const int tid  = threadIdx.x;
    const int lane = tid & 31;
    const int wid  = tid >> 5;
    const int wm   = wid & 3;
    const int wn   = wid >> 2;
    const int rowBase = blockIdx.x * 128;
    const int colBase = blockIdx.y * 64;

    float acc[2][4][4];
    #pragma unroll
    for (int a = 0; a < 2; a++)
        #pragma unroll
        for (int b = 0; b < 4; b++)
            #pragma unroll
            for (int c = 0; c < 4; c++) acc[a][b][c] = 0.f;

    auto load_slab = [&](int stage, int c) {
        uint32_t base = sb + stage * STG;
        int kb = c * 64;
        #pragma unroll
        for (int i = 0; i < 4; i++) {            // A: 128 rows x 8 chunks
            int f = tid + i * 256;
            int row = f >> 3, chn = f & 7;
            uint32_t sw = (uint32_t)(chn * 16) ^ (uint32_t)((row & 7) << 4);
            uint32_t da = base + row * 128 + sw;
            int gr = rowBase + row;
            if (gr < NN) {
                size_t off = (size_t)gr * KTOT + kb + chn * 8;
                cp16(da, Ah + off);
                cp16(da + 16384, Al + off);
            } else { zero16(da); zero16(da + 16384); }
        }
        #pragma unroll
        for (int i = 0; i < 2; i++) {            // B: 64 rows x 8 chunks
            int f = tid + i * 256;
            int row = f >> 3, chn = f & 7;
            uint32_t sw = (uint32_t)(chn * 16) ^ (uint32_t)((row & 7) << 4);
            uint32_t db = base + 32768 + row * 128 + sw;
            int gn = colBase + row;
            if (gn < Nc) {
                size_t off = (size_t)gn * KTOT + kb + chn * 8;
                cp16(db, Bhi + off);
                cp16(db + 8192, Blo + off);
            } else { zero16(db); zero16(db + 8192); }
        }
        asm volatile("cp.async.commit_group;" ::: "memory");
    };

    const uint32_t aRowIdx = (uint32_t)(lane & 15);
    const uint32_t aK16    = (uint32_t)((lane >> 4) << 4);     // byte offset 0/16
    const uint32_t bRowIdx = (uint32_t)((lane & 7) + ((lane >> 4) << 3));
    const uint32_t bK16    = (uint32_t)(((lane >> 3) & 1) << 4);

    load_slab(0, 0);

    for (int c = 0; c < CHUNKS; c++) {
        if (c + 1 < CHUNKS) {
            load_slab((c + 1) & 1, c + 1);
            asm volatile("cp.async.wait_group 1;" ::: "memory");
        } else {
            asm volatile("cp.async.wait_group 0;" ::: "memory");
        }
        __syncthreads();

        uint32_t bA = sb + (c & 1) * STG;
        uint32_t bB = bA + 32768;
        #pragma unroll
        for (int ks = 0; ks < 4; ks++) {
            uint32_t ah[2][4], al[2][4], bh[4][2], bl[4][2];
            #pragma unroll
            for (int mi = 0; mi < 2; mi++) {
                uint32_t row = wm * 32 + mi * 16 + aRowIdx;
                uint32_t cb = (uint32_t)(ks * 32) + aK16;
                uint32_t off = row * 128 + (cb ^ ((row & 7) << 4));
                ldsm4(ah[mi], bA + off);
                ldsm4(al[mi], bA + 16384 + off);
            }
            #pragma unroll
            for (int pr = 0; pr < 2; pr++) {
                uint32_t row = wn * 32 + pr * 16 + bRowIdx;
                uint32_t cb = (uint32_t)(ks * 32) + bK16;
                uint32_t off = row * 128 + (cb ^ ((row & 7) << 4));
                uint32_t t[4];
                ldsm4(t, bB + off);
                bh[pr*2][0] = t[0]; bh[pr*2][1] = t[1];
                bh[pr*2+1][0] = t[2]; bh[pr*2+1][1] = t[3];
                ldsm4(t, bB + 8192 + off);
                bl[pr*2][0] = t[0]; bl[pr*2][1] = t[1];
                bl[pr*2+1][0] = t[2]; bl[pr*2+1][1] = t[3];
            }
            #pragma unroll
            for (int mi = 0; mi < 2; mi++)
                #pragma unroll
                for (int ni = 0; ni < 4; ni++) {
                    mma16816(acc[mi][ni], ah[mi], bh[ni]);
                    mma16816(acc[mi][ni], ah[mi], bl[ni]);
                    mma16816(acc[mi][ni], al[mi], bh[ni]);
                }
        }
        if (c + 1 < CHUNKS) __syncthreads();
    }

    // ---- epilogue ----
    const int group = lane >> 2;
    const int qc    = (lane & 3) * 2;
    #pragma unroll
    for (int mi = 0; mi < 2; mi++) {
        int r0 = rowBase + wm * 32 + mi * 16 + group;
        int r1 = r0 + 8;
        #pragma unroll
        for (int ni = 0; ni < 4; ni++) {
            int c = colBase + wn * 32 + ni * 8 + qc;
            if (c >= Nc) continue;
            float b0 = __ldg(&bias[c]), b1 = __ldg(&bias[c + 1]);
            float2 v0, v1;
            v0.x = acc[mi][ni][0] + b0; v0.y = acc[mi][ni][1] + b1;
            v1.x = acc[mi][ni][2] + b0; v1.y = acc[mi][ni][3] + b1;
            if (EPI == 1) {
                v0.x = fmaxf(v0.x, 0.f); v0.y = fmaxf(v0.y, 0.f);
                v1.x = fmaxf(v1.x, 0.f); v1.y = fmaxf(v1.y, 0.f);
            }
            if (r0 < NN) {
                if (OUTMODE != 1) *(float2*)(Cf + (size_t)r0 * Nc + c) = v0;
                if (OUTMODE >= 1) {
                    uint32_t h, l; split2(v0.x, v0.y, h, l);
                    *(uint32_t*)(Ch + (size_t)r0 * Nc + c) = h;
                    *(uint32_t*)(Cl + (size_t)r0 * Nc + c) = l;
                }
            }
            if (r1 < NN) {
                if (OUTMODE != 1) *(float2*)(Cf + (size_t)r1 * Nc + c) = v1;
                if (OUTMODE >= 1) {
                    uint32_t h, l; split2(v1.x, v1.y, h, l);
                    *(uint32_t*)(Ch + (size_t)r1 * Nc + c) = h;
                    *(uint32_t*)(Cl + (size_t)r1 * Nc + c) = l;
                }
            }
        }
    }
}

// ---------------------------------------------------------------------------
extern "C" void kernel_launch(void* const* d_in, const int* in_sizes, int n_in,
                              void* d_out, int out_size) {
    const float* x_in   = (const float*)d_in[0];
    const float* eattr  = (const float*)d_in[1];
    const int*   eidx   = (const int*)  d_in[2];
    const float* node_W = (const float*)d_in[3];
    const float* node_b = (const float*)d_in[4];
    const float* edge_W = (const float*)d_in[5];
    const float* edge_b = (const float*)d_in[6];
    const float* W1     = (const float*)d_in[7];
    const float* b1     = (const float*)d_in[8];
    const float* W2     = (const float*)d_in[9];
    const float* b2     = (const float*)d_in[10];
    const float* eps    = (const float*)d_in[11];
    const float* lin_W  = (const float*)d_in[12];
    const float* lin_b  = (const float*)d_in[13];
    float* out = (float*)d_out;

    float *px, *pagg, *peam, *pseg, *pdeg, *pinv;
    __nv_bfloat16 *pwh, *pwl, *pch, *pcl, *ph1h, *ph1l, *pxh, *pxl;
    cudaGetSymbolAddress((void**)&px,   g_x);
    cudaGetSymbolAddress((void**)&pagg, g_agg);
    cudaGetSymbolAddress((void**)&peam, g_eam);
    cudaGetSymbolAddress((void**)&pseg, g_seg);
    cudaGetSymbolAddress((void**)&pdeg, g_deg);
    cudaGetSymbolAddress((void**)&pinv, g_inv);
    cudaGetSymbolAddress((void**)&pwh,  g_whi);
    cudaGetSymbolAddress((void**)&pwl,  g_wlo);
    cudaGetSymbolAddress((void**)&pch,  g_ch);
    cudaGetSymbolAddress((void**)&pcl,  g_cl);
    cudaGetSymbolAddress((void**)&ph1h, g_h1h);
    cudaGetSymbolAddress((void**)&ph1l, g_h1l);
    cudaGetSymbolAddress((void**)&pxh,  g_xh);
    cudaGetSymbolAddress((void**)&pxl,  g_xl);

    constexpr int SM_F32A = 55296;
    constexpr int SM_BF16 = 98304;
    auto setsm = [](const void* f, int b) {
        cudaFuncSetAttribute(f, cudaFuncAttributeMaxDynamicSharedMemorySize, b);
    };
    setsm((const void*)gemm_f32a<128, 0>, SM_F32A);
    setsm((const void*)gemm_f32a< 64, 2>, SM_F32A);
    setsm((const void*)gemm_bf16<128, 1, 1>, SM_BF16);
    setsm((const void*)gemm_bf16<256, 1, 2>, SM_BF16);
    setsm((const void*)gemm_bf16<128, 0, 0>, SM_BF16);

    // ---- weight prep (fused) ----
    wprep_all<<<920, 256>>>(node_W, edge_W, W1, W2, lin_W, pwh, pwl);

    // ---- graph preprocessing ----
    zero_kernel<<<256, 256>>>(pdeg, NN);
    zero_kernel<<<2048, 256>>>(pseg, NN * IN_EDGE);
    deg_kernel<<<(EE + 255) / 256, 256>>>(eidx, pdeg);
    inv_kernel<<<(NN + 255) / 256, 256>>>(pdeg, pinv);
    seg_scatter_kernel<<<(EE * 16 + 255) / 256, 256>>>(eattr, eidx, pseg);

    dim3 g2(TILES_M, 2), g4(TILES_M, 4);

    // node encoder: g_x = x @ node_W + node_b (fp32 out)
    gemm_f32a<128, 0><<<g2, 256, SM_F32A>>>(x_in, pwh, pwl, node_b, px, HH,
                                            nullptr, nullptr);
    // edge agg through encoder: g_eam = (seg @ edge_W)*inv + [deg>0]*edge_b
    gemm_f32a<64, 2><<<g2, 256, SM_F32A>>>(pseg, pwh + 16384, pwl + 16384,
                                           edge_b, peam, HH, pinv, pdeg);

    for (int l = 0; l < 3; l++) {
        zero_kernel<<<2048, 256>>>(pagg, NN * HH);
        x_scatter_kernel<<<EE * 32 / 256, 256>>>(eidx, px, pagg);
        combine_split<<<(NN * 32 + 255) / 256, 256>>>(px, pagg, peam, pinv, eps, l,
                                                      pch, pcl);
        // h1(split) = relu( combined @ W1[l] + b1[l] )
        gemm_bf16<128, 1, 1><<<g4, 256, SM_BF16>>>(pch, pcl,
            pwh + 24576 + l * 32768, pwl + 24576 + l * 32768,
            b1 + (size_t)l * HH2, nullptr, ph1h, ph1l, HH2);
        // x = relu( h1 @ W2[l] + b2[l] )  (fp32 + split out)
        gemm_bf16<256, 1, 2><<<g2, 256, SM_BF16>>>(ph1h, ph1l,
            pwh + 122880 + l * 32768, pwl + 122880 + l * 32768,
            b2 + (size_t)l * HH, px, pxh, pxl, HH);
    }

    // head: out = x @ lin_W + lin_b
    gemm_bf16<128, 0, 0><<<g2, 256, SM_BF16>>>(pxh, pxl, pwh + 221184, pwl + 221184,
        lin_b, out, nullptr, nullptr, OUTD);
}

// round 5
// speedup vs baseline: 2.4664x; 1.3380x over previous
#include <cuda_runtime.h>
#include <cuda_bf16.h>
#include <cstdint>

#define NN     50000
#define EE     625000
#define IN_EDGE 64
#define HH     128
#define HH2    256
#define OUTD   112
#define TILES_M 391   // ceil(50000/128)
#define NB     196    // ceil(50000/256)

// ---------------- scratch (device globals; no allocation allowed) ----------
__device__ __align__(16) float g_eam[NN * HH];
__device__ __align__(16) float g_seg[NN * IN_EDGE];
__device__ float g_inv[NN];
__device__ int   g_degi[NN];
__device__ int   g_rowptr[NN + 1];
__device__ int   g_cursor[NN];
__device__ int   g_bsum[NB];
__device__ int   g_boff[NB];
__device__ int   g_csrc[EE];
__device__ int   g_ceid[EE];

// split activations (bf16 hi/lo)
__device__ __align__(16) __nv_bfloat16 g_ch [NN * HH];    // combined, W1 input
__device__ __align__(16) __nv_bfloat16 g_cl [NN * HH];
__device__ __align__(16) __nv_bfloat16 g_h1h[NN * HH2];   // W1 output, W2 input
__device__ __align__(16) __nv_bfloat16 g_h1l[NN * HH2];
__device__ __align__(16) __nv_bfloat16 g_xh [NN * HH];    // node state (split)
__device__ __align__(16) __nv_bfloat16 g_xl [NN * HH];

// pre-split transposed weights, layout [N][K] bf16, hi/lo
__device__ __align__(16) __nv_bfloat16 g_whi[235520];
__device__ __align__(16) __nv_bfloat16 g_wlo[235520];

// ---------------------------------------------------------------------------
__device__ __forceinline__ uint32_t smem_u32(const void* p) {
    uint32_t a;
    asm("{ .reg .u64 t; cvta.to.shared.u64 t, %1; cvt.u32.u64 %0, t; }"
        : "=r"(a) : "l"(p));
    return a;
}
__device__ __forceinline__ void cp16(uint32_t dst, const void* src) {
    asm volatile("cp.async.cg.shared.global [%0], [%1], 16;"
                 :: "r"(dst), "l"(src) : "memory");
}
__device__ __forceinline__ void zero16(uint32_t dst) {
    asm volatile("st.shared.v4.b32 [%0], {%1,%1,%1,%1};" :: "r"(dst), "r"(0) : "memory");
}
__device__ __forceinline__ void ldsm4(uint32_t* r, uint32_t addr) {
    asm volatile("ldmatrix.sync.aligned.m8n8.x4.shared.b16 {%0,%1,%2,%3}, [%4];"
                 : "=r"(r[0]), "=r"(r[1]), "=r"(r[2]), "=r"(r[3]) : "r"(addr));
}
__device__ __forceinline__ void mma16816(float* d, const uint32_t* a, const uint32_t* b) {
    asm volatile("mma.sync.aligned.m16n8k16.row.col.f32.bf16.bf16.f32 "
                 "{%0,%1,%2,%3}, {%4,%5,%6,%7}, {%8,%9}, {%0,%1,%2,%3};"
                 : "+f"(d[0]), "+f"(d[1]), "+f"(d[2]), "+f"(d[3])
                 : "r"(a[0]), "r"(a[1]), "r"(a[2]), "r"(a[3]), "r"(b[0]), "r"(b[1]));
}
__device__ __forceinline__ void split2(float a, float b, uint32_t& hi, uint32_t& lo) {
    __nv_bfloat16 ha = __float2bfloat16(a), hb = __float2bfloat16(b);
    __nv_bfloat162 h = __halves2bfloat162(ha, hb);
    __nv_bfloat162 l = __halves2bfloat162(
        __float2bfloat16(a - __bfloat162float(ha)),
        __float2bfloat16(b - __bfloat162float(hb)));
    hi = *(uint32_t*)&h; lo = *(uint32_t*)&l;
}
__device__ __forceinline__ float2 unpack2(uint32_t h, uint32_t l) {
    __nv_bfloat162 hh = *(__nv_bfloat162*)&h;
    __nv_bfloat162 ll = *(__nv_bfloat162*)&l;
    return make_float2(__low2float(hh) + __low2float(ll),
                       __high2float(hh) + __high2float(ll));
}

// ---------------------------------------------------------------------------
// CSR build
// ---------------------------------------------------------------------------
__global__ void degi_kernel(const int* __restrict__ ei, int* __restrict__ d) {
    int e = blockIdx.x * blockDim.x + threadIdx.x;
    if (e < EE) atomicAdd(&d[ei[EE + e]], 1);
}
__global__ void inv_kernel(const int* __restrict__ d, float* __restrict__ inv) {
    int i = blockIdx.x * blockDim.x + threadIdx.x;
    if (i < NN) inv[i] = 1.0f / (float)max(d[i], 1);
}
__global__ void scan1(const int* __restrict__ d, int* __restrict__ bsum) {
    __shared__ int s[256];
    int i = blockIdx.x * 256 + threadIdx.x;
    s[threadIdx.x] = (i < NN) ? d[i] : 0;
    __syncthreads();
    for (int o = 128; o > 0; o >>= 1) {
        if (threadIdx.x < o) s[threadIdx.x] += s[threadIdx.x + o];
        __syncthreads();
    }
    if (threadIdx.x == 0) bsum[blockIdx.x] = s[0];
}
__global__ void scan2(const int* __restrict__ bsum, int* __restrict__ boff,
                      int* __restrict__ rowptr_last) {
    if (threadIdx.x == 0) {
        int acc = 0;
        for (int b = 0; b < NB; b++) { boff[b] = acc; acc += bsum[b]; }
        rowptr_last[0] = acc;
    }
}
__global__ void scan3(const int* __restrict__ d, const int* __restrict__ boff,
                      int* __restrict__ rowptr, int* __restrict__ cursor) {
    __shared__ int s[256];
    int i = blockIdx.x * 256 + threadIdx.x;
    int v = (i < NN) ? d[i] : 0;
    s[threadIdx.x] = v;
    __syncthreads();
    #pragma unroll
    for (int o = 1; o < 256; o <<= 1) {
        int t = (threadIdx.x >= o) ? s[threadIdx.x - o] : 0;
        __syncthreads();
        s[threadIdx.x] += t;
        __syncthreads();
    }
    if (i < NN) {
        int excl = s[threadIdx.x] - v + boff[blockIdx.x];
        rowptr[i] = excl;
        cursor[i] = excl;
    }
}
__global__ void csr_fill(const int* __restrict__ ei, int* __restrict__ cursor,
                         int* __restrict__ csrc, int* __restrict__ ceid) {
    int e = blockIdx.x * blockDim.x + threadIdx.x;
    if (e >= EE) return;
    int dst = __ldg(&ei[EE + e]);
    int p = atomicAdd(&cursor[dst], 1);
    csrc[p] = __ldg(&ei[e]);
    ceid[p] = e;
}

// seg[i] = sum of edge_attr rows with dst=i.  16 threads per node.
__global__ void seg_gather(const int* __restrict__ rowptr, const int* __restrict__ ceid,
                           const float* __restrict__ ea, float* __restrict__ seg) {
    int g = (blockIdx.x * blockDim.x + threadIdx.x) >> 4;
    if (g >= NN) return;
    int lane = threadIdx.x & 15;
    int beg = __ldg(&rowptr[g]), end = __ldg(&rowptr[g + 1]);
    float4 acc = make_float4(0.f, 0.f, 0.f, 0.f);
    for (int j = beg; j < end; j++) {
        int e = __ldg(&ceid[j]);
        float4 v = __ldg((const float4*)(ea + (size_t)e * IN_EDGE) + lane);
        acc.x += v.x; acc.y += v.y; acc.z += v.z; acc.w += v.w;
    }
    *(float4*)(seg + (size_t)g * IN_EDGE + lane * 4) = acc;
}

// fused: agg = sum_neighbors(x) ; c = (1+eps)*x + agg*inv + eam -> ch/cl (bf16 split)
// one warp per node; lane owns 4 features.
__global__ void gather_combine(const int* __restrict__ rowptr, const int* __restrict__ csrc,
                               const __nv_bfloat16* __restrict__ xh,
                               const __nv_bfloat16* __restrict__ xl,
                               const float* __restrict__ eam, const float* __restrict__ inv,
                               const float* __restrict__ eps_p, int layer,
                               __nv_bfloat16* __restrict__ ch, __nv_bfloat16* __restrict__ cl) {
    int w = (blockIdx.x * blockDim.x + threadIdx.x) >> 5;
    if (w >= NN) return;
    int lane = threadIdx.x & 31;
    int beg = __ldg(&rowptr[w]), end = __ldg(&rowptr[w + 1]);
    float a0 = 0.f, a1 = 0.f, a2 = 0.f, a3 = 0.f;
    for (int j = beg; j < end; j++) {
        int s = __ldg(&csrc[j]);
        uint2 hv = __ldg((const uint2*)(xh + (size_t)s * HH) + lane);
        uint2 lv = __ldg((const uint2*)(xl + (size_t)s * HH) + lane);
        float2 p01 = unpack2(hv.x, lv.x);
        float2 p23 = unpack2(hv.y, lv.y);
        a0 += p01.x; a1 += p01.y; a2 += p23.x; a3 += p23.y;
    }
    float iv = __ldg(&inv[w]);
    float epsv = 1.f + __ldg(&eps_p[layer]);
    uint2 hs = __ldg((const uint2*)(xh + (size_t)w * HH) + lane);
    uint2 ls = __ldg((const uint2*)(xl + (size_t)w * HH) + lane);
    float2 x01 = unpack2(hs.x, ls.x);
    float2 x23 = unpack2(hs.y, ls.y);
    float4 em = __ldg((const float4*)(eam + (size_t)w * HH) + lane);
    float v0 = epsv * x01.x + a0 * iv + em.x;
    float v1 = epsv * x01.y + a1 * iv + em.y;
    float v2 = epsv * x23.x + a2 * iv + em.z;
    float v3 = epsv * x23.y + a3 * iv + em.w;
    uint2 h, l;
    split2(v0, v1, h.x, l.x);
    split2(v2, v3, h.y, l.y);
    *(uint2*)(ch + (size_t)w * HH + lane * 4) = h;
    *(uint2*)(cl + (size_t)w * HH + lane * 4) = l;
}

// all weights: W[K][Nc] fp32 -> [N][K] bf16 hi/lo (transpose + split), fused
__global__ void wprep_all(const float* __restrict__ node_W, const float* __restrict__ edge_W,
                          const float* __restrict__ W1, const float* __restrict__ W2,
                          const float* __restrict__ lin_W,
                          __nv_bfloat16* __restrict__ hi, __nv_bfloat16* __restrict__ lo) {
    int i = blockIdx.x * blockDim.x + threadIdx.x;
    if (i >= 235520) return;
    const float* src; int K, Nc, idx;
    if (i < 16384)       { src = node_W;                 K = 128; Nc = 128; idx = i; }
    else if (i < 24576)  { src = edge_W;                 K =  64; Nc = 128; idx = i - 16384; }
    else if (i < 122880) { int j = i - 24576;  src = W1 + (j / 32768) * 32768; K = 128; Nc = 256; idx = j % 32768; }
    else if (i < 221184) { int j = i - 122880; src = W2 + (j / 32768) * 32768; K = 256; Nc = 128; idx = j % 32768; }
    else                 { src = lin_W;                  K = 128; Nc = 112; idx = i - 221184; }
    int n = idx / K, k = idx % K;
    float v = __ldg(&src[(size_t)k * Nc + n]);
    __nv_bfloat16 h = __float2bfloat16(v);
    hi[i] = h;
    lo[i] = __float2bfloat16(v - __bfloat162float(h));
}

// ---------------------------------------------------------------------------
// GEMM with fp32-A conversion loader (node & edge encoders).
// EPI: 0 = +bias; 2 = *inv + [deg>0]*bias
// OUTMODE: 0 = fp32 out; 1 = bf16 split out
// ---------------------------------------------------------------------------
#define ROWB 144
template <int KTOT, int EPI, int OUTMODE>
__global__ void __launch_bounds__(256, 2)
gemm_f32a(const float* __restrict__ A,
          const __nv_bfloat16* __restrict__ Bhi, const __nv_bfloat16* __restrict__ Blo,
          const float* __restrict__ bias, float* __restrict__ Cf,
          __nv_bfloat16* __restrict__ Ch, __nv_bfloat16* __restrict__ Cl, int Nc,
          const float* __restrict__ inv, const int* __restrict__ degi) {
    extern __shared__ char smem[];
    const uint32_t sb  = smem_u32(smem);
    const uint32_t sAh = sb,          sAl = sb + 18432;
    const uint32_t sBh = sb + 36864,  sBl = sb + 46080;

    const int tid  = threadIdx.x;
    const int lane = tid & 31;
    const int wid  = tid >> 5;
    const int wm   = wid & 3;
    const int wn   = wid >> 2;
    const int rowBase = blockIdx.x * 128;
    const int colBase = blockIdx.y * 64;

    float acc[2][4][4];
    #pragma unroll
    for (int a = 0; a < 2; a++)
        #pragma unroll
        for (int b = 0; b < 4; b++)
            #pragma unroll
            for (int c = 0; c < 4; c++) acc[a][b][c] = 0.f;

    const uint32_t aRow  = (uint32_t)(lane & 15);
    const uint32_t aKoff = (uint32_t)((lane >> 4) << 3);
    const uint32_t bRow  = (uint32_t)((lane & 7) + ((lane >> 4) << 3));
    const uint32_t bKoff = (uint32_t)(((lane >> 3) & 1) << 3);

    for (int kb = 0; kb < KTOT; kb += 64) {
        if (kb) __syncthreads();
        #pragma unroll
        for (int i = 0; i < 2; i++) {
            int f = tid + i * 256;
            int nrow = f >> 3, chunk = f & 7;
            uint32_t dh = sBh + nrow * ROWB + chunk * 16;
            uint32_t dl = sBl + nrow * ROWB + chunk * 16;
            int gn = colBase + nrow;
            if (gn < Nc) {
                size_t off = (size_t)gn * KTOT + kb + chunk * 8;
                cp16(dh, Bhi + off);
                cp16(dl, Blo + off);
            } else { zero16(dh); zero16(dl); }
        }
        asm volatile("cp.async.commit_group;" ::: "memory");

        #pragma unroll
        for (int i = 0; i < 8; i++) {
            int f = tid + i * 256;
            int row = f >> 4;
            int c4  = f & 15;
            int gr = rowBase + row;
            float4 v = make_float4(0.f, 0.f, 0.f, 0.f);
            if (gr < NN) v = __ldg((const float4*)(A + (size_t)gr * KTOT + kb + c4 * 4));
            uint32_t h01, h23, l01, l23;
            split2(v.x, v.y, h01, l01);
            split2(v.z, v.w, h23, l23);
            uint32_t addr = row * ROWB + c4 * 8;
            asm volatile("st.shared.v2.b32 [%0], {%1,%2};"
                         :: "r"(sAh + addr), "r"(h01), "r"(h23) : "memory");
            asm volatile("st.shared.v2.b32 [%0], {%1,%2};"
                         :: "r"(sAl + addr), "r"(l01), "r"(l23) : "memory");
        }
        asm volatile("cp.async.wait_group 0;" ::: "memory");
        __syncthreads();

        #pragma unroll
        for (int ks = 0; ks < 4; ks++) {
            uint32_t ah[2][4], al[2][4], bh[4][2], bl[4][2];
            #pragma unroll
            for (int mi = 0; mi < 2; mi++) {
                uint32_t off = (wm * 32 + mi * 16 + aRow) * ROWB + (ks * 16 + aKoff) * 2;
                ldsm4(ah[mi], sAh + off);
                ldsm4(al[mi], sAl + off);
            }
            #pragma unroll
            for (int pr = 0; pr < 2; pr++) {
                uint32_t off = (wn * 32 + pr * 16 + bRow) * ROWB + (ks * 16 + bKoff) * 2;
                uint32_t t[4];
                ldsm4(t, sBh + off);
                bh[pr*2][0] = t[0]; bh[pr*2][1] = t[1];
                bh[pr*2+1][0] = t[2]; bh[pr*2+1][1] = t[3];
                ldsm4(t, sBl + off);
                bl[pr*2][0] = t[0]; bl[pr*2][1] = t[1];
                bl[pr*2+1][0] = t[2]; bl[pr*2+1][1] = t[3];
            }
            #pragma unroll
            for (int mi = 0; mi < 2; mi++)
                #pragma unroll
                for (int ni = 0; ni < 4; ni++) {
                    mma16816(acc[mi][ni], ah[mi], bh[ni]);
                    mma16816(acc[mi][ni], ah[mi], bl[ni]);
                    mma16816(acc[mi][ni], al[mi], bh[ni]);
                }
        }
    }

    const int group = lane >> 2;
    const int qc    = (lane & 3) * 2;
    #pragma unroll
    for (int mi = 0; mi < 2; mi++) {
        int r0 = rowBase + wm * 32 + mi * 16 + group;
        int r1 = r0 + 8;
        float iv0 = 0.f, m0 = 0.f, iv1 = 0.f, m1 = 0.f;
        if (EPI == 2) {
            if (r0 < NN) { iv0 = __ldg(&inv[r0]); m0 = (__ldg(&degi[r0]) > 0) ? 1.f : 0.f; }
            if (r1 < NN) { iv1 = __ldg(&inv[r1]); m1 = (__ldg(&degi[r1]) > 0) ? 1.f : 0.f; }
        }
        #pragma unroll
        for (int ni = 0; ni < 4; ni++) {
            int c = colBase + wn * 32 + ni * 8 + qc;
            if (c >= Nc) continue;
            float b0 = __ldg(&bias[c]), b1 = __ldg(&bias[c + 1]);
            float2 v0, v1;
            if (EPI == 2) {
                v0.x = acc[mi][ni][0] * iv0 + m0 * b0;
                v0.y = acc[mi][ni][1] * iv0 + m0 * b1;
                v1.x = acc[mi][ni][2] * iv1 + m1 * b0;
                v1.y = acc[mi][ni][3] * iv1 + m1 * b1;
            } else {
                v0.x = acc[mi][ni][0] + b0; v0.y = acc[mi][ni][1] + b1;
                v1.x = acc[mi][ni][2] + b0; v1.y = acc[mi][ni][3] + b1;
            }
            if (r0 < NN) {
                if (OUTMODE == 0) *(float2*)(Cf + (size_t)r0 * Nc + c) = v0;
                else {
                    uint32_t h, l; split2(v0.x, v0.y, h, l);
                    *(uint32_t*)(Ch + (size_t)r0 * Nc + c) = h;
                    *(uint32_t*)(Cl + (size_t)r0 * Nc + c) = l;
                }
            }
            if (r1 < NN) {
                if (OUTMODE == 0) *(float2*)(Cf + (size_t)r1 * Nc + c) = v1;
                else {
                    uint32_t h, l; split2(v1.x, v1.y, h, l);
                    *(uint32_t*)(Ch + (size_t)r1 * Nc + c) = h;
                    *(uint32_t*)(Cl + (size_t)r1 * Nc + c) = l;
                }
            }
        }
    }
}

// ---------------------------------------------------------------------------
// Pipelined split-bf16 GEMM, A pre-split.
// EPI: 0 = +bias, 1 = relu(+bias)
// OUTMODE: 0 = fp32 only; 1 = bf16 split only
// ---------------------------------------------------------------------------
template <int KTOT, int EPI, int OUTMODE>
__global__ void __launch_bounds__(256, 2)
gemm_bf16(const __nv_bfloat16* __restrict__ Ah, const __nv_bfloat16* __restrict__ Al,
          const __nv_bfloat16* __restrict__ Bhi, const __nv_bfloat16* __restrict__ Blo,
          const float* __restrict__ bias, float* __restrict__ Cf,
          __nv_bfloat16* __restrict__ Ch, __nv_bfloat16* __restrict__ Cl, int Nc) {
    constexpr int CHUNKS = KTOT / 64;
    constexpr int STG = 49152;
    extern __shared__ char smem[];
    const uint32_t sb = smem_u32(smem);

    const int tid  = threadIdx.x;
    const int lane = tid & 31;
    const int wid  = tid >> 5;
    const int wm   = wid & 3;
    const int wn   = wid >> 2;
    const int rowBase = blockIdx.x * 128;
    const int colBase = blockIdx.y * 64;

    float acc[2][4][4];
    #pragma unroll
    for (int a = 0; a < 2; a++)
        #pragma unroll
        for (int b = 0; b < 4; b++)
            #pragma unroll
            for (int c = 0; c < 4; c++) acc[a][b][c] = 0.f;

    auto load_slab = [&](int stage, int c) {
        uint32_t base = sb + stage * STG;
        int kb = c * 64;
        #pragma unroll
        for (int i = 0; i < 4; i++) {
            int f = tid + i * 256;
            int row = f >> 3, chn = f & 7;
            uint32_t sw = (uint32_t)(chn * 16) ^ (uint32_t)((row & 7) << 4);
            uint32_t da = base + row * 128 + sw;
            int gr = rowBase + row;
            if (gr < NN) {
                size_t off = (size_t)gr * KTOT + kb + chn * 8;
                cp16(da, Ah + off);
                cp16(da + 16384, Al + off);
            } else { zero16(da); zero16(da + 16384); }
        }
        #pragma unroll
        for (int i = 0; i < 2; i++) {
            int f = tid + i * 256;
            int row = f >> 3, chn = f & 7;
            uint32_t sw = (uint32_t)(chn * 16) ^ (uint32_t)((row & 7) << 4);
            uint32_t db = base + 32768 + row * 128 + sw;
            int gn = colBase + row;
            if (gn < Nc) {
                size_t off = (size_t)gn * KTOT + kb + chn * 8;
                cp16(db, Bhi + off);
                cp16(db + 8192, Blo + off);
            } else { zero16(db); zero16(db + 8192); }
        }
        asm volatile("cp.async.commit_group;" ::: "memory");
    };

    const uint32_t aRowIdx = (uint32_t)(lane & 15);
    const uint32_t aK16    = (uint32_t)((lane >> 4) << 4);
    const uint32_t bRowIdx = (uint32_t)((lane & 7) + ((lane >> 4) << 3));
    const uint32_t bK16    = (uint32_t)(((lane >> 3) & 1) << 4);

    load_slab(0, 0);

    for (int c = 0; c < CHUNKS; c++) {
        if (c + 1 < CHUNKS) {
            load_slab((c + 1) & 1, c + 1);
            asm volatile("cp.async.wait_group 1;" ::: "memory");
        } else {
            asm volatile("cp.async.wait_group 0;" ::: "memory");
        }
        __syncthreads();

        uint32_t bA = sb + (c & 1) * STG;
        uint32_t bB = bA + 32768;
        #pragma unroll
        for (int ks = 0; ks < 4; ks++) {
            uint32_t ah[2][4], al[2][4], bh[4][2], bl[4][2];
            #pragma unroll
            for (int mi = 0; mi < 2; mi++) {
                uint32_t row = wm * 32 + mi * 16 + aRowIdx;
                uint32_t cb = (uint32_t)(ks * 32) + aK16;
                uint32_t off = row * 128 + (cb ^ ((row & 7) << 4));
                ldsm4(ah[mi], bA + off);
                ldsm4(al[mi], bA + 16384 + off);
            }
            #pragma unroll
            for (int pr = 0; pr < 2; pr++) {
                uint32_t row = wn * 32 + pr * 16 + bRowIdx;
                uint32_t cb = (uint32_t)(ks * 32) + bK16;
                uint32_t off = row * 128 + (cb ^ ((row & 7) << 4));
                uint32_t t[4];
                ldsm4(t, bB + off);
                bh[pr*2][0] = t[0]; bh[pr*2][1] = t[1];
                bh[pr*2+1][0] = t[2]; bh[pr*2+1][1] = t[3];
                ldsm4(t, bB + 8192 + off);
                bl[pr*2][0] = t[0]; bl[pr*2][1] = t[1];
                bl[pr*2+1][0] = t[2]; bl[pr*2+1][1] = t[3];
            }
            #pragma unroll
            for (int mi = 0; mi < 2; mi++)
                #pragma unroll
                for (int ni = 0; ni < 4; ni++) {
                    mma16816(acc[mi][ni], ah[mi], bh[ni]);
                    mma16816(acc[mi][ni], ah[mi], bl[ni]);
                    mma16816(acc[mi][ni], al[mi], bh[ni]);
                }
        }
        if (c + 1 < CHUNKS) __syncthreads();
    }

    const int group = lane >> 2;
    const int qc    = (lane & 3) * 2;
    #pragma unroll
    for (int mi = 0; mi < 2; mi++) {
        int r0 = rowBase + wm * 32 + mi * 16 + group;
        int r1 = r0 + 8;
        #pragma unroll
        for (int ni = 0; ni < 4; ni++) {
            int c = colBase + wn * 32 + ni * 8 + qc;
            if (c >= Nc) continue;
            float b0 = __ldg(&bias[c]), b1 = __ldg(&bias[c + 1]);
            float2 v0, v1;
            v0.x = acc[mi][ni][0] + b0; v0.y = acc[mi][ni][1] + b1;
            v1.x = acc[mi][ni][2] + b0; v1.y = acc[mi][ni][3] + b1;
            if (EPI == 1) {
                v0.x = fmaxf(v0.x, 0.f); v0.y = fmaxf(v0.y, 0.f);
                v1.x = fmaxf(v1.x, 0.f); v1.y = fmaxf(v1.y, 0.f);
            }
            if (r0 < NN) {
                if (OUTMODE == 0) *(float2*)(Cf + (size_t)r0 * Nc + c) = v0;
                else {
                    uint32_t h, l; split2(v0.x, v0.y, h, l);
                    *(uint32_t*)(Ch + (size_t)r0 * Nc + c) = h;
                    *(uint32_t*)(Cl + (size_t)r0 * Nc + c) = l;
                }
            }
            if (r1 < NN) {
                if (OUTMODE == 0) *(float2*)(Cf + (size_t)r1 * Nc + c) = v1;
                else {
                    uint32_t h, l; split2(v1.x, v1.y, h, l);
                    *(uint32_t*)(Ch + (size_t)r1 * Nc + c) = h;
                    *(uint32_t*)(Cl + (size_t)r1 * Nc + c) = l;
                }
            }
        }
    }
}

// ---------------------------------------------------------------------------
extern "C" void kernel_launch(void* const* d_in, const int* in_sizes, int n_in,
                              void* d_out, int out_size) {
    const float* x_in   = (const float*)d_in[0];
    const float* eattr  = (const float*)d_in[1];
    const int*   eidx   = (const int*)  d_in[2];
    const float* node_W = (const float*)d_in[3];
    const float* node_b = (const float*)d_in[4];
    const float* edge_W = (const float*)d_in[5];
    const float* edge_b = (const float*)d_in[6];
    const float* W1     = (const float*)d_in[7];
    const float* b1     = (const float*)d_in[8];
    const float* W2     = (const float*)d_in[9];
    const float* b2     = (const float*)d_in[10];
    const float* eps    = (const float*)d_in[11];
    const float* lin_W  = (const float*)d_in[12];
    const float* lin_b  = (const float*)d_in[13];
    float* out = (float*)d_out;

    float *peam, *pseg, *pinv;
    int *pdegi, *prowptr, *pcursor, *pbsum, *pboff, *pcsrc, *pceid;
    __nv_bfloat16 *pwh, *pwl, *pch, *pcl, *ph1h, *ph1l, *pxh, *pxl;
    cudaGetSymbolAddress((void**)&peam, g_eam);
    cudaGetSymbolAddress((void**)&pseg, g_seg);
    cudaGetSymbolAddress((void**)&pinv, g_inv);
    cudaGetSymbolAddress((void**)&pdegi, g_degi);
    cudaGetSymbolAddress((void**)&prowptr, g_rowptr);
    cudaGetSymbolAddress((void**)&pcursor, g_cursor);
    cudaGetSymbolAddress((void**)&pbsum, g_bsum);
    cudaGetSymbolAddress((void**)&pboff, g_boff);
    cudaGetSymbolAddress((void**)&pcsrc, g_csrc);
    cudaGetSymbolAddress((void**)&pceid, g_ceid);
    cudaGetSymbolAddress((void**)&pwh,  g_whi);
    cudaGetSymbolAddress((void**)&pwl,  g_wlo);
    cudaGetSymbolAddress((void**)&pch,  g_ch);
    cudaGetSymbolAddress((void**)&pcl,  g_cl);
    cudaGetSymbolAddress((void**)&ph1h, g_h1h);
    cudaGetSymbolAddress((void**)&ph1l, g_h1l);
    cudaGetSymbolAddress((void**)&pxh,  g_xh);
    cudaGetSymbolAddress((void**)&pxl,  g_xl);

    constexpr int SM_F32A = 55296;
    constexpr int SM_BF16 = 98304;
    auto setsm = [](const void* f, int b) {
        cudaFuncSetAttribute(f, cudaFuncAttributeMaxDynamicSharedMemorySize, b);
    };
    setsm((const void*)gemm_f32a<128, 0, 1>, SM_F32A);
    setsm((const void*)gemm_f32a< 64, 2, 0>, SM_F32A);
    setsm((const void*)gemm_bf16<128, 1, 1>, SM_BF16);
    setsm((const void*)gemm_bf16<256, 1, 1>, SM_BF16);
    setsm((const void*)gemm_bf16<128, 0, 0>, SM_BF16);

    // ---- weight prep ----
    wprep_all<<<920, 256>>>(node_W, edge_W, W1, W2, lin_W, pwh, pwl);

    // ---- CSR build ----
    cudaMemsetAsync(pdegi, 0, NN * sizeof(int));
    degi_kernel<<<(EE + 255) / 256, 256>>>(eidx, pdegi);
    inv_kernel<<<(NN + 255) / 256, 256>>>(pdegi, pinv);
    scan1<<<NB, 256>>>(pdegi, pbsum);
    scan2<<<1, 32>>>(pbsum, pboff, prowptr + NN);
    scan3<<<NB, 256>>>(pdegi, pboff, prowptr, pcursor);
    csr_fill<<<(EE + 255) / 256, 256>>>(eidx, pcursor, pcsrc, pceid);

    // seg[i] = sum edge_attr over incoming edges
    seg_gather<<<(NN * 16 + 255) / 256, 256>>>(prowptr, pceid, eattr, pseg);

    dim3 g2(TILES_M, 2), g4(TILES_M, 4);

    // node encoder: x(split) = x_in @ node_W + node_b
    gemm_f32a<128, 0, 1><<<g2, 256, SM_F32A>>>(x_in, pwh, pwl, node_b,
        nullptr, pxh, pxl, HH, nullptr, nullptr);
    // edge agg through encoder: eam = (seg @ edge_W)*inv + [deg>0]*edge_b (fp32)
    gemm_f32a<64, 2, 0><<<g2, 256, SM_F32A>>>(pseg, pwh + 16384, pwl + 16384,
        edge_b, peam, nullptr, nullptr, HH, pinv, pdegi);

    for (int l = 0; l < 3; l++) {
        // fused gather + combine + split
        gather_combine<<<(NN * 32 + 255) / 256, 256>>>(prowptr, pcsrc, pxh, pxl,
            peam, pinv, eps, l, pch, pcl);
        // h1(split) = relu( c @ W1[l] + b1[l] )
        gemm_bf16<128, 1, 1><<<g4, 256, SM_BF16>>>(pch, pcl,
            pwh + 24576 + l * 32768, pwl + 24576 + l * 32768,
            b1 + (size_t)l * HH2, nullptr, ph1h, ph1l, HH2);
        // x(split) = relu( h1 @ W2[l] + b2[l] )
        gemm_bf16<256, 1, 1><<<g2, 256, SM_BF16>>>(ph1h, ph1l,
            pwh + 122880 + l * 32768, pwl + 122880 + l * 32768,
            b2 + (size_t)l * HH, nullptr, pxh, pxl, HH);
    }

    // head: out = x @ lin_W + lin_b
    gemm_bf16<128, 0, 0><<<g2, 256, SM_BF16>>>(pxh, pxl, pwh + 221184, pwl + 221184,
        lin_b, out, nullptr, nullptr, OUTD);
}